// round 4
// baseline (speedup 1.0000x reference)
#include <cuda_runtime.h>
#include <math.h>

#define F 64
#define KSEL 256
#define NMAX 20000
#define EMAX 320000
#define ETMAX (NMAX + EMAX)
#define NEG_INF (-3.402823466e38f)

// ---------------- scratch (static __device__, no allocation) ----------------
__device__ float g_h[NMAX * F];
__device__ float g_x1[NMAX * F];
__device__ float g_x2[NMAX * F];
__device__ float g_xqp[NMAX * F];
__device__ float g_xq[NMAX * F];
__device__ float g_xc[NMAX * F];
__device__ float g_dis[NMAX];
__device__ float g_qa[NMAX], g_pa[NMAX];
__device__ float g_av[NMAX], g_bv[NMAX], g_cv[NMAX], g_fit[NMAX];
__device__ float g_score[ETMAX];
__device__ int   g_rowS[ETMAX], g_colS[ETMAX];
__device__ int   g_cnt[NMAX], g_ptr[NMAX + 1], g_wofs[NMAX], g_inv[NMAX];
__device__ unsigned long long g_cand[16 * 256];
__device__ int   g_perm[KSEL];
__device__ float g_fitk[KSEL];
__device__ int   g_entR[ETMAX], g_entK[ETMAX];
__device__ float g_entV[ETMAX];
__device__ int   g_nent;
__device__ float g_AS[(size_t)NMAX * KSEL];

// ---------------- helpers ----------------
__device__ __forceinline__ float wredsum(float v) {
    #pragma unroll
    for (int d = 16; d; d >>= 1) v += __shfl_xor_sync(0xFFFFFFFFu, v, d);
    return v;
}
__device__ __forceinline__ float wredmax(float v) {
    #pragma unroll
    for (int d = 16; d; d >>= 1) v = fmaxf(v, __shfl_xor_sync(0xFFFFFFFFu, v, d));
    return v;
}
__device__ __forceinline__ unsigned long long make_key(float f, int i) {
    unsigned u = __float_as_uint(f);
    u = (u & 0x80000000u) ? ~u : (u | 0x80000000u);
    return ((unsigned long long)u << 32) | (unsigned)(0xFFFFFFFFu - (unsigned)i);
}
template <int NSORT>
__device__ void bitonic_desc(unsigned long long* s) {
    int t = threadIdx.x;
    for (int k = 2; k <= NSORT; k <<= 1) {
        for (int j = k >> 1; j > 0; j >>= 1) {
            for (int i = t; i < NSORT; i += blockDim.x) {
                int ixj = i ^ j;
                if (ixj > i) {
                    unsigned long long a = s[i], b = s[ixj];
                    bool sw = ((i & k) == 0) ? (a < b) : (a > b);
                    if (sw) { s[i] = b; s[ixj] = a; }
                }
            }
            __syncthreads();
        }
    }
}

// ---------------- CSR build ----------------
__global__ void k_count(const int* __restrict__ ei, int E, int Nn) {
    int e = blockIdx.x * blockDim.x + threadIdx.x;
    int Et = E + Nn;
    if (e >= Et) return;
    int c = (e < E) ? ei[E + e] : (e - E);
    atomicAdd(&g_cnt[c], 1);
}

__global__ void __launch_bounds__(1024) k_scan(int Nn) {
    __shared__ int warpsum[32];
    int t = threadIdx.x, lane = t & 31, wid = t >> 5;
    int offset = 0;
    for (int base = 0; base < Nn; base += 1024) {
        int i = base + t;
        int v = (i < Nn) ? g_cnt[i] : 0;
        int x = v;
        #pragma unroll
        for (int d = 1; d < 32; d <<= 1) {
            int y = __shfl_up_sync(0xFFFFFFFFu, x, d);
            if (lane >= d) x += y;
        }
        if (lane == 31) warpsum[wid] = x;
        __syncthreads();
        if (wid == 0) {
            int s = warpsum[lane];
            #pragma unroll
            for (int d = 1; d < 32; d <<= 1) {
                int y = __shfl_up_sync(0xFFFFFFFFu, s, d);
                if (lane >= d) s += y;
            }
            warpsum[lane] = s;
        }
        __syncthreads();
        int ex = x - v + (wid > 0 ? warpsum[wid - 1] : 0);
        int val = offset + ex;
        if (i < Nn) { g_ptr[i] = val; g_wofs[i] = val; }
        offset += warpsum[31];
        __syncthreads();
    }
    if (t == 0) g_ptr[Nn] = offset;
}

__global__ void k_dis(int Nn) {
    int i = blockIdx.x * blockDim.x + threadIdx.x;
    if (i >= Nn) return;
    g_dis[i] = rsqrtf((float)(g_ptr[i + 1] - g_ptr[i]));
}

__global__ void k_scatter(const int* __restrict__ ei, int E, int Nn) {
    int e = blockIdx.x * blockDim.x + threadIdx.x;
    int Et = E + Nn;
    if (e >= Et) return;
    int r, c;
    if (e < E) { r = ei[e]; c = ei[E + e]; } else { r = e - E; c = e - E; }
    int pos = atomicAdd(&g_wofs[c], 1);
    g_rowS[pos] = r;
    g_colS[pos] = c;
}

// ---------------- dense matmul (N x 64) @ (64 x 64) (+bias) ----------------
__global__ void __launch_bounds__(256) k_matmul(const float* __restrict__ X,
                                                const float* __restrict__ W,
                                                const float* __restrict__ bias,
                                                float* __restrict__ Y, int n) {
    __shared__ float Ws[F * F];
    __shared__ float Xs[32 * F];
    int t = threadIdx.x;
    for (int i = t; i < F * F; i += 256) Ws[i] = W[i];
    int r0 = blockIdx.x * 32;
    for (int i = t; i < 32 * F; i += 256) {
        int r = r0 + i / F;
        Xs[i] = (r < n) ? X[r0 * F + i] : 0.f;
    }
    __syncthreads();
    int tx = t & 63, ty = t >> 6;
    float acc[8] = {0, 0, 0, 0, 0, 0, 0, 0};
    for (int k = 0; k < F; k++) {
        float wv = Ws[k * F + tx];
        #pragma unroll
        for (int j = 0; j < 8; j++) acc[j] += Xs[(ty + 4 * j) * F + k] * wv;
    }
    float bb = bias ? bias[tx] : 0.f;
    #pragma unroll
    for (int j = 0; j < 8; j++) {
        int r = r0 + ty + 4 * j;
        if (r < n) Y[r * F + tx] = acc[j] + bb;
    }
}

// ---------------- segment ops (warp per node over CSR) ----------------
__global__ void k_gcnagg(const float* __restrict__ h, const float* __restrict__ b,
                         float* __restrict__ out, int n) {
    int w = (blockIdx.x * blockDim.x + threadIdx.x) >> 5;
    int l = threadIdx.x & 31;
    if (w >= n) return;
    int s = g_ptr[w], e = g_ptr[w + 1];
    float dc = g_dis[w];
    float a0 = 0.f, a1 = 0.f;
    for (int p = s; p < e; p++) {
        int r = g_rowS[p];
        float nm = dc * g_dis[r];
        float2 hv = *(const float2*)(h + r * F + l * 2);
        a0 += nm * hv.x; a1 += nm * hv.y;
    }
    a0 += b[2 * l]; a1 += b[2 * l + 1];
    out[w * F + 2 * l] = fmaxf(a0, 0.f);
    out[w * F + 2 * l + 1] = fmaxf(a1, 0.f);
}

__global__ void k_segmax(const float* __restrict__ x2, float* __restrict__ out, int n) {
    int w = (blockIdx.x * blockDim.x + threadIdx.x) >> 5;
    int l = threadIdx.x & 31;
    if (w >= n) return;
    int s = g_ptr[w], e = g_ptr[w + 1];
    float a0 = NEG_INF, a1 = NEG_INF;
    for (int p = s; p < e; p++) {
        int r = g_rowS[p];
        float2 hv = *(const float2*)(x2 + r * F + l * 2);
        a0 = fmaxf(a0, hv.x); a1 = fmaxf(a1, hv.y);
    }
    out[w * F + 2 * l] = a0;
    out[w * F + 2 * l + 1] = a1;
}

__global__ void k_qapa(const float* __restrict__ attW, int n) {
    int w = (blockIdx.x * blockDim.x + threadIdx.x) >> 5;
    int l = threadIdx.x & 31;
    if (w >= n) return;
    float2 q = *(const float2*)(g_xq + w * F + 2 * l);
    float2 p = *(const float2*)(g_x2 + w * F + 2 * l);
    float s1 = q.x * attW[2 * l] + q.y * attW[2 * l + 1];
    float s2 = p.x * attW[F + 2 * l] + p.y * attW[F + 2 * l + 1];
    s1 = wredsum(s1); s2 = wredsum(s2);
    if (l == 0) { g_qa[w] = s1; g_pa[w] = s2; }
}

__global__ void k_score(const float* __restrict__ attb, int Et) {
    int e = blockIdx.x * blockDim.x + threadIdx.x;
    if (e >= Et) return;
    float s = g_qa[g_colS[e]] + g_pa[g_rowS[e]] + attb[0];
    g_score[e] = (s >= 0.f) ? s : 0.2f * s;
}

__global__ void k_softmax(int n) {
    int w = (blockIdx.x * blockDim.x + threadIdx.x) >> 5;
    int l = threadIdx.x & 31;
    if (w >= n) return;
    int s = g_ptr[w], e = g_ptr[w + 1];
    float m = NEG_INF;
    for (int p = s + l; p < e; p += 32) m = fmaxf(m, g_score[p]);
    m = wredmax(m);
    float sum = 0.f;
    for (int p = s + l; p < e; p += 32) sum += expf(g_score[p] - m);
    sum = wredsum(sum);
    float invs = 1.f / sum;
    for (int p = s + l; p < e; p += 32) g_score[p] = expf(g_score[p] - m) * invs;
}

__global__ void k_xc(int n) {
    int w = (blockIdx.x * blockDim.x + threadIdx.x) >> 5;
    int l = threadIdx.x & 31;
    if (w >= n) return;
    int s = g_ptr[w], e = g_ptr[w + 1];
    float a0 = 0.f, a1 = 0.f;
    for (int p = s; p < e; p++) {
        int r = g_rowS[p];
        float sc = g_score[p];
        float2 hv = *(const float2*)(g_x2 + r * F + l * 2);
        a0 += sc * hv.x; a1 += sc * hv.y;
    }
    g_xc[w * F + 2 * l] = a0;
    g_xc[w * F + 2 * l + 1] = a1;
}

__global__ void k_ledots(const float* __restrict__ le1W, const float* __restrict__ le1b,
                         const float* __restrict__ le2W, const float* __restrict__ le3W, int n) {
    int w = (blockIdx.x * blockDim.x + threadIdx.x) >> 5;
    int l = threadIdx.x & 31;
    if (w >= n) return;
    float2 v = *(const float2*)(g_xc + w * F + 2 * l);
    float s1 = v.x * le1W[2 * l] + v.y * le1W[2 * l + 1];
    float s2 = v.x * le2W[2 * l] + v.y * le2W[2 * l + 1];
    float s3 = v.x * le3W[2 * l] + v.y * le3W[2 * l + 1];
    s1 = wredsum(s1); s2 = wredsum(s2); s3 = wredsum(s3);
    if (l == 0) { g_av[w] = s1 + le1b[0]; g_bv[w] = s2; g_cv[w] = s3; }
}

__global__ void k_invinit(int n) {
    int i = blockIdx.x * blockDim.x + threadIdx.x;
    if (i < n) g_inv[i] = KSEL;
}

__global__ void k_fitness(const float* __restrict__ le3b, int n) {
    int w = (blockIdx.x * blockDim.x + threadIdx.x) >> 5;
    int l = threadIdx.x & 31;
    if (w >= n) return;
    int s = g_ptr[w], e = g_ptr[w + 1];
    float sum = 0.f;
    for (int p = s + l; p < e; p += 32) sum += g_av[g_rowS[p]];
    sum = wredsum(sum);
    if (l == 0) {
        float deg = (float)(e - s);
        float val = sum - deg * g_bv[w] + g_cv[w] + le3b[0];
        g_fit[w] = 1.f / (1.f + expf(-val));
    }
}

// ---------------- exact top-K (jax semantics) ----------------
__global__ void __launch_bounds__(1024) k_topk1(int n) {
    __shared__ unsigned long long s[2048];
    int t = threadIdx.x;
    int base = blockIdx.x * 2048;
    for (int j = t; j < 2048; j += 1024) {
        int i = base + j;
        s[j] = (i < n) ? make_key(g_fit[i], i) : 0ULL;
    }
    __syncthreads();
    bitonic_desc<2048>(s);
    if (t < 256) g_cand[blockIdx.x * 256 + t] = s[t];
}

__global__ void __launch_bounds__(1024) k_topk2(int n2) {
    __shared__ unsigned long long s[4096];
    int t = threadIdx.x;
    for (int j = t; j < 4096; j += 1024) s[j] = (j < n2) ? g_cand[j] : 0ULL;
    __syncthreads();
    bitonic_desc<4096>(s);
    if (t < KSEL) {
        unsigned long long key = s[t];
        int idx = (int)(0xFFFFFFFFu - (unsigned)(key & 0xFFFFFFFFu));
        g_perm[t] = idx;
        g_fitk[t] = g_fit[idx];
        g_inv[idx] = t;
    }
}

// ---------------- sparse S / AS / A_new ----------------
__global__ void k_entries(int Et) {
    int e = blockIdx.x * blockDim.x + threadIdx.x;
    if (e >= Et) return;
    int k = g_inv[g_colS[e]];
    if (k < KSEL) {
        int p = atomicAdd(&g_nent, 1);
        g_entR[p] = g_rowS[e];
        g_entK[p] = k;
        g_entV[p] = g_score[e];
    }
}

__global__ void k_AS() {
    int i0 = blockIdx.x * blockDim.x + threadIdx.x;
    int stride = gridDim.x * blockDim.x;
    int ne = g_nent;
    for (int i = i0; i < ne; i += stride) {
        int v = g_entR[i];
        int k = g_entK[i];
        float val = g_entV[i];
        int s = g_ptr[v], e = g_ptr[v + 1];
        for (int p = s; p < e; p++)
            atomicAdd(&g_AS[(size_t)g_rowS[p] * KSEL + k], val);
    }
}

__global__ void k_Anew(float* __restrict__ outA) {
    int w = (blockIdx.x * blockDim.x + threadIdx.x) >> 5;
    int l = threadIdx.x & 31;
    int nw = (gridDim.x * blockDim.x) >> 5;
    int ne = g_nent;
    for (int i = w; i < ne; i += nw) {
        int r = g_entR[i];
        int k1 = g_entK[i];
        float v = g_entV[i];
        const float4* asr = (const float4*)(g_AS + (size_t)r * KSEL);
        float4 x0 = asr[l * 2], x1 = asr[l * 2 + 1];
        float* dst = outA + k1 * KSEL + l * 8;
        atomicAdd(dst + 0, v * x0.x);
        atomicAdd(dst + 1, v * x0.y);
        atomicAdd(dst + 2, v * x0.z);
        atomicAdd(dst + 3, v * x0.w);
        atomicAdd(dst + 4, v * x1.x);
        atomicAdd(dst + 5, v * x1.y);
        atomicAdd(dst + 6, v * x1.z);
        atomicAdd(dst + 7, v * x1.w);
    }
}

__global__ void k_final(float* __restrict__ out) {
    int t = blockIdx.x * blockDim.x + threadIdx.x;
    if (t < KSEL * F) {
        int k = t / F, f = t % F;
        out[t] = g_xc[g_perm[k] * F + f] * g_fitk[k];
    }
    if (t < KSEL) {
        out[KSEL * F + KSEL * KSEL + t] = (float)g_perm[t];
        out[KSEL * F + t * KSEL + t] = 1.0f;
    }
}

// ---------------- launch ----------------
extern "C" void kernel_launch(void* const* d_in, const int* in_sizes, int n_in,
                              void* d_out, int out_size) {
    const float* x     = (const float*)d_in[0];
    const int*   ei    = (const int*)d_in[1];
    const float* W0    = (const float*)d_in[2];
    const float* b0    = (const float*)d_in[3];
    const float* W1    = (const float*)d_in[4];
    const float* b1    = (const float*)d_in[5];
    const float* linW  = (const float*)d_in[6];
    const float* linb  = (const float*)d_in[7];
    const float* attW  = (const float*)d_in[8];
    const float* attb  = (const float*)d_in[9];
    const float* le1W  = (const float*)d_in[10];
    const float* le1b  = (const float*)d_in[11];
    const float* le2W  = (const float*)d_in[12];
    const float* le3W  = (const float*)d_in[13];
    const float* le3b  = (const float*)d_in[14];
    float* out = (float*)d_out;

    int N  = in_sizes[0] / F;
    int E  = in_sizes[1] / 2;
    int Et = E + N;

    // resolve device addresses of scratch globals (host shadows are NOT device ptrs!)
    void *vp;
    cudaGetSymbolAddress(&vp, g_h);    float* p_h   = (float*)vp;
    cudaGetSymbolAddress(&vp, g_x1);   float* p_x1  = (float*)vp;
    cudaGetSymbolAddress(&vp, g_x2);   float* p_x2  = (float*)vp;
    cudaGetSymbolAddress(&vp, g_xqp);  float* p_xqp = (float*)vp;
    cudaGetSymbolAddress(&vp, g_xq);   float* p_xq  = (float*)vp;
    cudaGetSymbolAddress(&vp, g_cnt);  void*  p_cnt = vp;
    cudaGetSymbolAddress(&vp, g_nent); void*  p_nent= vp;
    cudaGetSymbolAddress(&vp, g_AS);   void*  p_AS  = vp;

    cudaMemsetAsync(p_cnt, 0, (size_t)N * sizeof(int));
    cudaMemsetAsync(p_nent, 0, sizeof(int));
    cudaMemsetAsync(p_AS, 0, (size_t)N * KSEL * sizeof(float));
    cudaMemsetAsync(out + KSEL * F, 0, (size_t)KSEL * KSEL * sizeof(float));

    int tEB = (Et + 255) / 256;   // edge-parallel blocks
    int nWB = (N + 7) / 8;        // warp-per-node blocks (256 thr = 8 warps)
    int nTB = (N + 255) / 256;
    int mmB = (N + 31) / 32;

    k_count<<<tEB, 256>>>(ei, E, N);
    k_scan<<<1, 1024>>>(N);
    k_dis<<<nTB, 256>>>(N);
    k_scatter<<<tEB, 256>>>(ei, E, N);

    k_matmul<<<mmB, 256>>>(x, W0, nullptr, p_h, N);
    k_gcnagg<<<nWB, 256>>>(p_h, b0, p_x1, N);
    k_matmul<<<mmB, 256>>>(p_x1, W1, nullptr, p_h, N);
    k_gcnagg<<<nWB, 256>>>(p_h, b1, p_x2, N);

    k_segmax<<<nWB, 256>>>(p_x2, p_xqp, N);
    k_matmul<<<mmB, 256>>>(p_xqp, linW, linb, p_xq, N);
    k_qapa<<<nWB, 256>>>(attW, N);
    k_score<<<tEB, 256>>>(attb, Et);
    k_softmax<<<nWB, 256>>>(N);
    k_xc<<<nWB, 256>>>(N);

    k_ledots<<<nWB, 256>>>(le1W, le1b, le2W, le3W, N);
    k_invinit<<<nTB, 256>>>(N);
    k_fitness<<<nWB, 256>>>(le3b, N);

    int nb1 = (N + 2047) / 2048;
    k_topk1<<<nb1, 1024>>>(N);
    k_topk2<<<1, 1024>>>(nb1 * 256);

    k_entries<<<tEB, 256>>>(Et);
    k_AS<<<256, 256>>>();
    k_Anew<<<512, 256>>>(out + KSEL * F);
    k_final<<<(KSEL * F + 255) / 256, 256>>>(out);

    (void)n_in; (void)out_size;
}

// round 5
// speedup vs baseline: 1.0659x; 1.0659x over previous
#include <cuda_runtime.h>
#include <math.h>

#define F 64
#define KSEL 256
#define NMAX 20000
#define EMAX 320000
#define ETMAX (NMAX + EMAX)
#define NEG_INF (-3.402823466e38f)

// ---------------- scratch (static __device__, no allocation) ----------------
__device__ float g_h[NMAX * F];
__device__ float g_x1[NMAX * F];
__device__ float g_x2[NMAX * F];
__device__ float g_xqp[NMAX * F];
__device__ float g_xq[NMAX * F];
__device__ float g_xc[NMAX * F];
__device__ float g_dis[NMAX];
__device__ float g_qa[NMAX], g_pa[NMAX];
__device__ float g_av[NMAX], g_bv[NMAX], g_cv[NMAX], g_fit[NMAX];
__device__ float g_score[ETMAX];
__device__ int   g_rowS[ETMAX], g_colS[ETMAX];
__device__ int   g_cnt[NMAX], g_ptr[NMAX + 1], g_wofs[NMAX], g_inv[NMAX];
__device__ unsigned long long g_cand[16 * 256];
__device__ int   g_perm[KSEL];
__device__ float g_fitk[KSEL];
__device__ int   g_entR[ETMAX], g_entK[ETMAX];
__device__ float g_entV[ETMAX];
__device__ int   g_nent;
__device__ float g_AS[(size_t)NMAX * KSEL];

// ---------------- helpers ----------------
__device__ __forceinline__ float wredsum(float v) {
    #pragma unroll
    for (int d = 16; d; d >>= 1) v += __shfl_xor_sync(0xFFFFFFFFu, v, d);
    return v;
}
__device__ __forceinline__ float wredmax(float v) {
    #pragma unroll
    for (int d = 16; d; d >>= 1) v = fmaxf(v, __shfl_xor_sync(0xFFFFFFFFu, v, d));
    return v;
}
__device__ __forceinline__ unsigned long long make_key(float f, int i) {
    unsigned u = __float_as_uint(f);
    u = (u & 0x80000000u) ? ~u : (u | 0x80000000u);
    return ((unsigned long long)u << 32) | (unsigned)(0xFFFFFFFFu - (unsigned)i);
}
template <int NSORT>
__device__ void bitonic_desc(unsigned long long* s) {
    int t = threadIdx.x;
    for (int k = 2; k <= NSORT; k <<= 1) {
        for (int j = k >> 1; j > 0; j >>= 1) {
            for (int i = t; i < NSORT; i += blockDim.x) {
                int ixj = i ^ j;
                if (ixj > i) {
                    unsigned long long a = s[i], b = s[ixj];
                    bool sw = ((i & k) == 0) ? (a < b) : (a > b);
                    if (sw) { s[i] = b; s[ixj] = a; }
                }
            }
            __syncthreads();
        }
    }
}

// ---------------- init: clear counters, init inv ----------------
__global__ void k_init(int Nn) {
    int i = blockIdx.x * blockDim.x + threadIdx.x;
    if (i < Nn) { g_cnt[i] = 0; g_inv[i] = KSEL; }
    if (i == 0) g_nent = 0;
}

// ---------------- CSR build ----------------
__global__ void k_count(const int* __restrict__ ei, int E, int Nn) {
    int e = blockIdx.x * blockDim.x + threadIdx.x;
    int Et = E + Nn;
    if (e >= Et) return;
    int c = (e < E) ? ei[E + e] : (e - E);
    atomicAdd(&g_cnt[c], 1);
}

// scan counts -> ptr/wofs, also deg -> dis
__global__ void __launch_bounds__(1024) k_scan(int Nn) {
    __shared__ int warpsum[32];
    int t = threadIdx.x, lane = t & 31, wid = t >> 5;
    int offset = 0;
    for (int base = 0; base < Nn; base += 1024) {
        int i = base + t;
        int v = (i < Nn) ? g_cnt[i] : 0;
        int x = v;
        #pragma unroll
        for (int d = 1; d < 32; d <<= 1) {
            int y = __shfl_up_sync(0xFFFFFFFFu, x, d);
            if (lane >= d) x += y;
        }
        if (lane == 31) warpsum[wid] = x;
        __syncthreads();
        if (wid == 0) {
            int s = warpsum[lane];
            #pragma unroll
            for (int d = 1; d < 32; d <<= 1) {
                int y = __shfl_up_sync(0xFFFFFFFFu, s, d);
                if (lane >= d) s += y;
            }
            warpsum[lane] = s;
        }
        __syncthreads();
        int ex = x - v + (wid > 0 ? warpsum[wid - 1] : 0);
        int val = offset + ex;
        if (i < Nn) {
            g_ptr[i] = val; g_wofs[i] = val;
            g_dis[i] = rsqrtf((float)v);
        }
        offset += warpsum[31];
        __syncthreads();
    }
    if (t == 0) g_ptr[Nn] = offset;
}

__global__ void k_scatter(const int* __restrict__ ei, int E, int Nn) {
    int e = blockIdx.x * blockDim.x + threadIdx.x;
    int Et = E + Nn;
    if (e >= Et) return;
    int r, c;
    if (e < E) { r = ei[e]; c = ei[E + e]; } else { r = e - E; c = e - E; }
    int pos = atomicAdd(&g_wofs[c], 1);
    g_rowS[pos] = r;
    g_colS[pos] = c;
}

// ---------------- dense matmul (N x 64) @ (64 x 64) (+bias) ----------------
__global__ void __launch_bounds__(256) k_matmul(const float* __restrict__ X,
                                                const float* __restrict__ W,
                                                const float* __restrict__ bias,
                                                float* __restrict__ Y, int n) {
    __shared__ float Ws[F * F];
    __shared__ float Xs[32 * F];
    int t = threadIdx.x;
    for (int i = t; i < F * F; i += 256) Ws[i] = W[i];
    int r0 = blockIdx.x * 32;
    for (int i = t; i < 32 * F; i += 256) {
        int r = r0 + i / F;
        Xs[i] = (r < n) ? X[r0 * F + i] : 0.f;
    }
    __syncthreads();
    int tx = t & 63, ty = t >> 6;
    float acc[8] = {0, 0, 0, 0, 0, 0, 0, 0};
    for (int k = 0; k < F; k++) {
        float wv = Ws[k * F + tx];
        #pragma unroll
        for (int j = 0; j < 8; j++) acc[j] += Xs[(ty + 4 * j) * F + k] * wv;
    }
    float bb = bias ? bias[tx] : 0.f;
    #pragma unroll
    for (int j = 0; j < 8; j++) {
        int r = r0 + ty + 4 * j;
        if (r < n) Y[r * F + tx] = acc[j] + bb;
    }
}

// matmul variant with fused qa = Y_row . attW[0:64] epilogue
__global__ void __launch_bounds__(256) k_matmul_qa(const float* __restrict__ X,
                                                   const float* __restrict__ W,
                                                   const float* __restrict__ bias,
                                                   const float* __restrict__ attW,
                                                   float* __restrict__ Y, int n) {
    __shared__ float Ws[F * F];
    __shared__ float Xs[32 * F];
    __shared__ float qs[32][2];
    int t = threadIdx.x;
    for (int i = t; i < F * F; i += 256) Ws[i] = W[i];
    int r0 = blockIdx.x * 32;
    for (int i = t; i < 32 * F; i += 256) {
        int r = r0 + i / F;
        Xs[i] = (r < n) ? X[r0 * F + i] : 0.f;
    }
    __syncthreads();
    int tx = t & 63, ty = t >> 6;
    float acc[8] = {0, 0, 0, 0, 0, 0, 0, 0};
    for (int k = 0; k < F; k++) {
        float wv = Ws[k * F + tx];
        #pragma unroll
        for (int j = 0; j < 8; j++) acc[j] += Xs[(ty + 4 * j) * F + k] * wv;
    }
    float bb = bias[tx];
    float aw = attW[tx];
    int half = (t >> 5) & 1;
    #pragma unroll
    for (int j = 0; j < 8; j++) {
        int r = r0 + ty + 4 * j;
        float val = acc[j] + bb;
        if (r < n) Y[r * F + tx] = val;
        float p = val * aw;
        p = wredsum(p);
        if ((t & 31) == 0) qs[ty + 4 * j][half] = p;
    }
    __syncthreads();
    if (t < 32) {
        int r = r0 + t;
        if (r < n) g_qa[r] = qs[t][0] + qs[t][1];
    }
}

// ---------------- segment gathers: 2 edges/iter, float4/lane ----------------
// gcn aggregate: out[w] = relu(sum nm * h[row]) + bias; optional pa epilogue
template <bool WITH_PA>
__global__ void k_gcnagg(const float* __restrict__ h, const float* __restrict__ b,
                         const float* __restrict__ attW, float* __restrict__ out, int n) {
    int w = (blockIdx.x * blockDim.x + threadIdx.x) >> 5;
    int l = threadIdx.x & 31;
    if (w >= n) return;
    int half = l >> 4, f4 = l & 15;
    int s = g_ptr[w], e = g_ptr[w + 1];
    float dc = g_dis[w];
    float4 acc = make_float4(0.f, 0.f, 0.f, 0.f);
    for (int p = s + half; p < e; p += 2) {
        int r = g_rowS[p];
        float nm = dc * g_dis[r];
        float4 hv = *(const float4*)(h + r * F + f4 * 4);
        acc.x += nm * hv.x; acc.y += nm * hv.y;
        acc.z += nm * hv.z; acc.w += nm * hv.w;
    }
    acc.x += __shfl_xor_sync(0xFFFFFFFFu, acc.x, 16);
    acc.y += __shfl_xor_sync(0xFFFFFFFFu, acc.y, 16);
    acc.z += __shfl_xor_sync(0xFFFFFFFFu, acc.z, 16);
    acc.w += __shfl_xor_sync(0xFFFFFFFFu, acc.w, 16);
    float4 bb = *(const float4*)(b + f4 * 4);
    acc.x = fmaxf(acc.x + bb.x, 0.f);
    acc.y = fmaxf(acc.y + bb.y, 0.f);
    acc.z = fmaxf(acc.z + bb.z, 0.f);
    acc.w = fmaxf(acc.w + bb.w, 0.f);
    if (half == 0) *(float4*)(out + w * F + f4 * 4) = acc;
    if (WITH_PA) {
        float part = 0.f;
        if (half == 0) {
            float4 aw = *(const float4*)(attW + F + f4 * 4);
            part = acc.x * aw.x + acc.y * aw.y + acc.z * aw.z + acc.w * aw.w;
        }
        part = wredsum(part);
        if (l == 0) g_pa[w] = part;
    }
}

__global__ void k_segmax(const float* __restrict__ x2, float* __restrict__ out, int n) {
    int w = (blockIdx.x * blockDim.x + threadIdx.x) >> 5;
    int l = threadIdx.x & 31;
    if (w >= n) return;
    int half = l >> 4, f4 = l & 15;
    int s = g_ptr[w], e = g_ptr[w + 1];
    float4 acc = make_float4(NEG_INF, NEG_INF, NEG_INF, NEG_INF);
    for (int p = s + half; p < e; p += 2) {
        int r = g_rowS[p];
        float4 hv = *(const float4*)(x2 + r * F + f4 * 4);
        acc.x = fmaxf(acc.x, hv.x); acc.y = fmaxf(acc.y, hv.y);
        acc.z = fmaxf(acc.z, hv.z); acc.w = fmaxf(acc.w, hv.w);
    }
    acc.x = fmaxf(acc.x, __shfl_xor_sync(0xFFFFFFFFu, acc.x, 16));
    acc.y = fmaxf(acc.y, __shfl_xor_sync(0xFFFFFFFFu, acc.y, 16));
    acc.z = fmaxf(acc.z, __shfl_xor_sync(0xFFFFFFFFu, acc.z, 16));
    acc.w = fmaxf(acc.w, __shfl_xor_sync(0xFFFFFFFFu, acc.w, 16));
    if (half == 0) *(float4*)(out + w * F + f4 * 4) = acc;
}

// softmax with fused raw-score computation (score = leaky(qa[col] + pa[row] + b))
__global__ void k_softmax(const float* __restrict__ attb, int n) {
    int w = (blockIdx.x * blockDim.x + threadIdx.x) >> 5;
    int l = threadIdx.x & 31;
    if (w >= n) return;
    int s = g_ptr[w], e = g_ptr[w + 1];
    float qb = g_qa[w] + attb[0];
    float m = NEG_INF;
    for (int p = s + l; p < e; p += 32) {
        float sc = qb + g_pa[g_rowS[p]];
        sc = (sc >= 0.f) ? sc : 0.2f * sc;
        g_score[p] = sc;
        m = fmaxf(m, sc);
    }
    m = wredmax(m);
    float sum = 0.f;
    for (int p = s + l; p < e; p += 32) sum += expf(g_score[p] - m);
    sum = wredsum(sum);
    float invs = 1.f / sum;
    for (int p = s + l; p < e; p += 32) g_score[p] = expf(g_score[p] - m) * invs;
}

// xc = sum score * x2[row], with fused le1/le2/le3 dot epilogue
__global__ void k_xc(const float* __restrict__ le1W, const float* __restrict__ le1b,
                     const float* __restrict__ le2W, const float* __restrict__ le3W, int n) {
    int w = (blockIdx.x * blockDim.x + threadIdx.x) >> 5;
    int l = threadIdx.x & 31;
    if (w >= n) return;
    int half = l >> 4, f4 = l & 15;
    int s = g_ptr[w], e = g_ptr[w + 1];
    float4 acc = make_float4(0.f, 0.f, 0.f, 0.f);
    for (int p = s + half; p < e; p += 2) {
        int r = g_rowS[p];
        float sc = g_score[p];
        float4 hv = *(const float4*)(g_x2 + r * F + f4 * 4);
        acc.x += sc * hv.x; acc.y += sc * hv.y;
        acc.z += sc * hv.z; acc.w += sc * hv.w;
    }
    acc.x += __shfl_xor_sync(0xFFFFFFFFu, acc.x, 16);
    acc.y += __shfl_xor_sync(0xFFFFFFFFu, acc.y, 16);
    acc.z += __shfl_xor_sync(0xFFFFFFFFu, acc.z, 16);
    acc.w += __shfl_xor_sync(0xFFFFFFFFu, acc.w, 16);
    float s1 = 0.f, s2 = 0.f, s3 = 0.f;
    if (half == 0) {
        *(float4*)(g_xc + w * F + f4 * 4) = acc;
        float4 w1 = *(const float4*)(le1W + f4 * 4);
        float4 w2 = *(const float4*)(le2W + f4 * 4);
        float4 w3 = *(const float4*)(le3W + f4 * 4);
        s1 = acc.x * w1.x + acc.y * w1.y + acc.z * w1.z + acc.w * w1.w;
        s2 = acc.x * w2.x + acc.y * w2.y + acc.z * w2.z + acc.w * w2.w;
        s3 = acc.x * w3.x + acc.y * w3.y + acc.z * w3.z + acc.w * w3.w;
    }
    s1 = wredsum(s1); s2 = wredsum(s2); s3 = wredsum(s3);
    if (l == 0) { g_av[w] = s1 + le1b[0]; g_bv[w] = s2; g_cv[w] = s3; }
}

__global__ void k_fitness(const float* __restrict__ le3b, int n) {
    int w = (blockIdx.x * blockDim.x + threadIdx.x) >> 5;
    int l = threadIdx.x & 31;
    if (w >= n) return;
    int s = g_ptr[w], e = g_ptr[w + 1];
    float sum = 0.f;
    for (int p = s + l; p < e; p += 32) sum += g_av[g_rowS[p]];
    sum = wredsum(sum);
    if (l == 0) {
        float deg = (float)(e - s);
        float val = sum - deg * g_bv[w] + g_cv[w] + le3b[0];
        g_fit[w] = 1.f / (1.f + expf(-val));
    }
}

// ---------------- exact top-K (jax semantics) ----------------
__global__ void __launch_bounds__(1024) k_topk1(int n) {
    __shared__ unsigned long long s[2048];
    int t = threadIdx.x;
    int base = blockIdx.x * 2048;
    for (int j = t; j < 2048; j += 1024) {
        int i = base + j;
        s[j] = (i < n) ? make_key(g_fit[i], i) : 0ULL;
    }
    __syncthreads();
    bitonic_desc<2048>(s);
    if (t < 256) g_cand[blockIdx.x * 256 + t] = s[t];
}

__global__ void __launch_bounds__(1024) k_topk2(int n2) {
    __shared__ unsigned long long s[4096];
    int t = threadIdx.x;
    for (int j = t; j < 4096; j += 1024) s[j] = (j < n2) ? g_cand[j] : 0ULL;
    __syncthreads();
    bitonic_desc<4096>(s);
    if (t < KSEL) {
        unsigned long long key = s[t];
        int idx = (int)(0xFFFFFFFFu - (unsigned)(key & 0xFFFFFFFFu));
        g_perm[t] = idx;
        g_fitk[t] = g_fit[idx];
        g_inv[idx] = t;
    }
}

// ---------------- sparse S entries + AS scatter (fused) ----------------
__global__ void k_entries(int Et) {
    int e = blockIdx.x * blockDim.x + threadIdx.x;
    if (e >= Et) return;
    int k = g_inv[g_colS[e]];
    if (k < KSEL) {
        int r = g_rowS[e];
        float val = g_score[e];
        int p = atomicAdd(&g_nent, 1);
        g_entR[p] = r;
        g_entK[p] = k;
        g_entV[p] = val;
        int s = g_ptr[r], en = g_ptr[r + 1];
        for (int q = s; q < en; q++)
            atomicAdd(&g_AS[(size_t)g_rowS[q] * KSEL + k], val);
    }
}

__global__ void k_Anew(float* __restrict__ outA) {
    int w = (blockIdx.x * blockDim.x + threadIdx.x) >> 5;
    int l = threadIdx.x & 31;
    int nw = (gridDim.x * blockDim.x) >> 5;
    int ne = g_nent;
    for (int i = w; i < ne; i += nw) {
        int r = g_entR[i];
        int k1 = g_entK[i];
        float v = g_entV[i];
        const float4* asr = (const float4*)(g_AS + (size_t)r * KSEL);
        float4 x0 = asr[l * 2], x1 = asr[l * 2 + 1];
        float* dst = outA + k1 * KSEL + l * 8;
        atomicAdd(dst + 0, v * x0.x);
        atomicAdd(dst + 1, v * x0.y);
        atomicAdd(dst + 2, v * x0.z);
        atomicAdd(dst + 3, v * x0.w);
        atomicAdd(dst + 4, v * x1.x);
        atomicAdd(dst + 5, v * x1.y);
        atomicAdd(dst + 6, v * x1.z);
        atomicAdd(dst + 7, v * x1.w);
    }
}

__global__ void k_final(float* __restrict__ out) {
    int t = blockIdx.x * blockDim.x + threadIdx.x;
    if (t < KSEL * F) {
        int k = t / F, f = t % F;
        out[t] = g_xc[g_perm[k] * F + f] * g_fitk[k];
    }
    if (t < KSEL) {
        out[KSEL * F + KSEL * KSEL + t] = (float)g_perm[t];
        out[KSEL * F + t * KSEL + t] = 1.0f;
    }
}

// ---------------- launch ----------------
extern "C" void kernel_launch(void* const* d_in, const int* in_sizes, int n_in,
                              void* d_out, int out_size) {
    const float* x     = (const float*)d_in[0];
    const int*   ei    = (const int*)d_in[1];
    const float* W0    = (const float*)d_in[2];
    const float* b0    = (const float*)d_in[3];
    const float* W1    = (const float*)d_in[4];
    const float* b1    = (const float*)d_in[5];
    const float* linW  = (const float*)d_in[6];
    const float* linb  = (const float*)d_in[7];
    const float* attW  = (const float*)d_in[8];
    const float* attb  = (const float*)d_in[9];
    const float* le1W  = (const float*)d_in[10];
    const float* le1b  = (const float*)d_in[11];
    const float* le2W  = (const float*)d_in[12];
    const float* le3W  = (const float*)d_in[13];
    const float* le3b  = (const float*)d_in[14];
    float* out = (float*)d_out;

    int N  = in_sizes[0] / F;
    int E  = in_sizes[1] / 2;
    int Et = E + N;

    void* vp;
    cudaGetSymbolAddress(&vp, g_h);   float* p_h   = (float*)vp;
    cudaGetSymbolAddress(&vp, g_x1);  float* p_x1  = (float*)vp;
    cudaGetSymbolAddress(&vp, g_x2);  float* p_x2  = (float*)vp;
    cudaGetSymbolAddress(&vp, g_xqp); float* p_xqp = (float*)vp;
    cudaGetSymbolAddress(&vp, g_xq);  float* p_xq  = (float*)vp;
    cudaGetSymbolAddress(&vp, g_AS);  void*  p_AS  = vp;

    cudaMemsetAsync(p_AS, 0, (size_t)N * KSEL * sizeof(float));
    cudaMemsetAsync(out + KSEL * F, 0, (size_t)KSEL * KSEL * sizeof(float));

    int tEB = (Et + 255) / 256;   // edge-parallel blocks
    int nWB = (N + 7) / 8;        // warp-per-node blocks (256 thr = 8 warps)
    int nTB = (N + 255) / 256;
    int mmB = (N + 31) / 32;

    k_init<<<nTB, 256>>>(N);
    k_count<<<tEB, 256>>>(ei, E, N);
    k_scan<<<1, 1024>>>(N);
    k_scatter<<<tEB, 256>>>(ei, E, N);

    k_matmul<<<mmB, 256>>>(x, W0, nullptr, p_h, N);
    k_gcnagg<false><<<nWB, 256>>>(p_h, b0, nullptr, p_x1, N);
    k_matmul<<<mmB, 256>>>(p_x1, W1, nullptr, p_h, N);
    k_gcnagg<true><<<nWB, 256>>>(p_h, b1, attW, p_x2, N);

    k_segmax<<<nWB, 256>>>(p_x2, p_xqp, N);
    k_matmul_qa<<<mmB, 256>>>(p_xqp, linW, linb, attW, p_xq, N);
    k_softmax<<<nWB, 256>>>(attb, N);
    k_xc<<<nWB, 256>>>(le1W, le1b, le2W, le3W, N);
    k_fitness<<<nWB, 256>>>(le3b, N);

    int nb1 = (N + 2047) / 2048;
    k_topk1<<<nb1, 1024>>>(N);
    k_topk2<<<1, 1024>>>(nb1 * 256);

    k_entries<<<tEB, 256>>>(Et);
    k_Anew<<<512, 256>>>(out + KSEL * F);
    k_final<<<(KSEL * F + 255) / 256, 256>>>(out);

    (void)n_in; (void)out_size;
}

// round 6
// speedup vs baseline: 1.0713x; 1.0050x over previous
#include <cuda_runtime.h>
#include <math.h>

#define F 64
#define KSEL 256
#define NMAX 20000
#define EMAX 320000
#define ETMAX (NMAX + EMAX)
#define NEG_INF (-3.402823466e38f)

// ---------------- scratch (static __device__, zero-initialized) ----------------
__device__ float g_h[NMAX * F];
__device__ float g_x1[NMAX * F];
__device__ float g_x2[NMAX * F];
__device__ float g_xqp[NMAX * F];
__device__ float g_xq[NMAX * F];
__device__ float g_xc[NMAX * F];
__device__ float g_dis[NMAX];
__device__ float g_qa[NMAX], g_pa[NMAX];
__device__ float g_av[NMAX], g_bv[NMAX], g_cv[NMAX], g_fit[NMAX];
__device__ float g_score[ETMAX];
__device__ int   g_rowS[ETMAX];
__device__ int   g_cnt[NMAX], g_ptr[NMAX + 1], g_wofs[NMAX], g_inv[NMAX];
__device__ unsigned long long g_cand[16 * 256];
__device__ int   g_perm[KSEL];
__device__ float g_fitk[KSEL];
__device__ int   g_entR[ETMAX], g_entK[ETMAX];
__device__ float g_entV[ETMAX];
__device__ int   g_nent;
__device__ float g_AS[(size_t)NMAX * KSEL];

// ---------------- helpers ----------------
__device__ __forceinline__ float wredsum(float v) {
    #pragma unroll
    for (int d = 16; d; d >>= 1) v += __shfl_xor_sync(0xFFFFFFFFu, v, d);
    return v;
}
__device__ __forceinline__ float wredmax(float v) {
    #pragma unroll
    for (int d = 16; d; d >>= 1) v = fmaxf(v, __shfl_xor_sync(0xFFFFFFFFu, v, d));
    return v;
}
__device__ __forceinline__ unsigned long long make_key(float f, int i) {
    unsigned u = __float_as_uint(f);
    u = (u & 0x80000000u) ? ~u : (u | 0x80000000u);
    return ((unsigned long long)u << 32) | (unsigned)(0xFFFFFFFFu - (unsigned)i);
}
template <int NSORT>
__device__ void bitonic_desc(unsigned long long* s) {
    int t = threadIdx.x;
    for (int k = 2; k <= NSORT; k <<= 1) {
        for (int j = k >> 1; j > 0; j >>= 1) {
            for (int i = t; i < NSORT; i += blockDim.x) {
                int ixj = i ^ j;
                if (ixj > i) {
                    unsigned long long a = s[i], b = s[ixj];
                    bool sw = ((i & k) == 0) ? (a < b) : (a > b);
                    if (sw) { s[i] = b; s[ixj] = a; }
                }
            }
            __syncthreads();
        }
    }
}

// ---------------- CSR build ----------------
// count only real edges (self loops folded in as +1 during scan)
__global__ void k_count(const int* __restrict__ ei, int E) {
    int e = blockIdx.x * blockDim.x + threadIdx.x;
    if (e >= E) return;
    atomicAdd(&g_cnt[ei[E + e]], 1);
}

// scan (counts+1) -> ptr/wofs, deg -> dis; RESETS g_cnt to 0 after reading
__global__ void __launch_bounds__(1024) k_scan(int Nn) {
    __shared__ int warpsum[32];
    int t = threadIdx.x, lane = t & 31, wid = t >> 5;
    int offset = 0;
    for (int base = 0; base < Nn; base += 1024) {
        int i = base + t;
        int v = 0;
        if (i < Nn) { v = g_cnt[i] + 1; g_cnt[i] = 0; }
        int x = v;
        #pragma unroll
        for (int d = 1; d < 32; d <<= 1) {
            int y = __shfl_up_sync(0xFFFFFFFFu, x, d);
            if (lane >= d) x += y;
        }
        if (lane == 31) warpsum[wid] = x;
        __syncthreads();
        if (wid == 0) {
            int s = warpsum[lane];
            #pragma unroll
            for (int d = 1; d < 32; d <<= 1) {
                int y = __shfl_up_sync(0xFFFFFFFFu, s, d);
                if (lane >= d) s += y;
            }
            warpsum[lane] = s;
        }
        __syncthreads();
        int ex = x - v + (wid > 0 ? warpsum[wid - 1] : 0);
        int val = offset + ex;
        if (i < Nn) {
            g_ptr[i] = val; g_wofs[i] = val;
            g_dis[i] = rsqrtf((float)v);
        }
        offset += warpsum[31];
        __syncthreads();
    }
    if (t == 0) g_ptr[Nn] = offset;
}

__global__ void k_scatter(const int* __restrict__ ei, int E, int Nn) {
    int e = blockIdx.x * blockDim.x + threadIdx.x;
    int Et = E + Nn;
    if (e >= Et) return;
    int r, c;
    if (e < E) { r = ei[e]; c = ei[E + e]; } else { r = e - E; c = e - E; }
    int pos = atomicAdd(&g_wofs[c], 1);
    g_rowS[pos] = r;
}

// ---------------- dense matmul (N x 64) @ (64 x 64) (+bias) ----------------
__global__ void __launch_bounds__(256) k_matmul(const float* __restrict__ X,
                                                const float* __restrict__ W,
                                                const float* __restrict__ bias,
                                                float* __restrict__ Y, int n) {
    __shared__ float Ws[F * F];
    __shared__ float Xs[32 * F];
    int t = threadIdx.x;
    for (int i = t; i < F * F; i += 256) Ws[i] = W[i];
    int r0 = blockIdx.x * 32;
    for (int i = t; i < 32 * F; i += 256) {
        int r = r0 + i / F;
        Xs[i] = (r < n) ? X[r0 * F + i] : 0.f;
    }
    __syncthreads();
    int tx = t & 63, ty = t >> 6;
    float acc[8] = {0, 0, 0, 0, 0, 0, 0, 0};
    for (int k = 0; k < F; k++) {
        float wv = Ws[k * F + tx];
        #pragma unroll
        for (int j = 0; j < 8; j++) acc[j] += Xs[(ty + 4 * j) * F + k] * wv;
    }
    float bb = bias ? bias[tx] : 0.f;
    #pragma unroll
    for (int j = 0; j < 8; j++) {
        int r = r0 + ty + 4 * j;
        if (r < n) Y[r * F + tx] = acc[j] + bb;
    }
}

// matmul variant with fused qa = Y_row . attW[0:64] epilogue
__global__ void __launch_bounds__(256) k_matmul_qa(const float* __restrict__ X,
                                                   const float* __restrict__ W,
                                                   const float* __restrict__ bias,
                                                   const float* __restrict__ attW,
                                                   float* __restrict__ Y, int n) {
    __shared__ float Ws[F * F];
    __shared__ float Xs[32 * F];
    __shared__ float qs[32][2];
    int t = threadIdx.x;
    for (int i = t; i < F * F; i += 256) Ws[i] = W[i];
    int r0 = blockIdx.x * 32;
    for (int i = t; i < 32 * F; i += 256) {
        int r = r0 + i / F;
        Xs[i] = (r < n) ? X[r0 * F + i] : 0.f;
    }
    __syncthreads();
    int tx = t & 63, ty = t >> 6;
    float acc[8] = {0, 0, 0, 0, 0, 0, 0, 0};
    for (int k = 0; k < F; k++) {
        float wv = Ws[k * F + tx];
        #pragma unroll
        for (int j = 0; j < 8; j++) acc[j] += Xs[(ty + 4 * j) * F + k] * wv;
    }
    float bb = bias[tx];
    float aw = attW[tx];
    int half = (t >> 5) & 1;
    #pragma unroll
    for (int j = 0; j < 8; j++) {
        int r = r0 + ty + 4 * j;
        float val = acc[j] + bb;
        if (r < n) Y[r * F + tx] = val;
        float p = val * aw;
        p = wredsum(p);
        if ((t & 31) == 0) qs[ty + 4 * j][half] = p;
    }
    __syncthreads();
    if (t < 32) {
        int r = r0 + t;
        if (r < n) g_qa[r] = qs[t][0] + qs[t][1];
    }
}

// ---------------- segment gathers: 4 edges in flight per warp ----------------
template <bool WITH_PA>
__global__ void k_gcnagg(const float* __restrict__ h, const float* __restrict__ b,
                         const float* __restrict__ attW, float* __restrict__ out, int n) {
    int w = (blockIdx.x * blockDim.x + threadIdx.x) >> 5;
    int l = threadIdx.x & 31;
    if (w >= n) return;
    int half = l >> 4, f4 = l & 15;
    int s = g_ptr[w], e = g_ptr[w + 1];
    float dc = g_dis[w];
    float4 a0 = make_float4(0.f, 0.f, 0.f, 0.f);
    float4 a1 = make_float4(0.f, 0.f, 0.f, 0.f);
    int p = s + half;
    for (; p + 2 < e; p += 4) {
        int r0 = g_rowS[p], r1 = g_rowS[p + 2];
        float n0 = dc * g_dis[r0], n1 = dc * g_dis[r1];
        float4 h0 = *(const float4*)(h + r0 * F + f4 * 4);
        float4 h1 = *(const float4*)(h + r1 * F + f4 * 4);
        a0.x += n0 * h0.x; a0.y += n0 * h0.y; a0.z += n0 * h0.z; a0.w += n0 * h0.w;
        a1.x += n1 * h1.x; a1.y += n1 * h1.y; a1.z += n1 * h1.z; a1.w += n1 * h1.w;
    }
    if (p < e) {
        int r0 = g_rowS[p];
        float n0 = dc * g_dis[r0];
        float4 h0 = *(const float4*)(h + r0 * F + f4 * 4);
        a0.x += n0 * h0.x; a0.y += n0 * h0.y; a0.z += n0 * h0.z; a0.w += n0 * h0.w;
    }
    a0.x += a1.x; a0.y += a1.y; a0.z += a1.z; a0.w += a1.w;
    a0.x += __shfl_xor_sync(0xFFFFFFFFu, a0.x, 16);
    a0.y += __shfl_xor_sync(0xFFFFFFFFu, a0.y, 16);
    a0.z += __shfl_xor_sync(0xFFFFFFFFu, a0.z, 16);
    a0.w += __shfl_xor_sync(0xFFFFFFFFu, a0.w, 16);
    float4 bb = *(const float4*)(b + f4 * 4);
    a0.x = fmaxf(a0.x + bb.x, 0.f);
    a0.y = fmaxf(a0.y + bb.y, 0.f);
    a0.z = fmaxf(a0.z + bb.z, 0.f);
    a0.w = fmaxf(a0.w + bb.w, 0.f);
    if (half == 0) *(float4*)(out + w * F + f4 * 4) = a0;
    if (WITH_PA) {
        float part = 0.f;
        if (half == 0) {
            float4 aw = *(const float4*)(attW + F + f4 * 4);
            part = a0.x * aw.x + a0.y * aw.y + a0.z * aw.z + a0.w * aw.w;
        }
        part = wredsum(part);
        if (l == 0) g_pa[w] = part;
    }
}

__global__ void k_segmax(const float* __restrict__ x2, float* __restrict__ out, int n) {
    int w = (blockIdx.x * blockDim.x + threadIdx.x) >> 5;
    int l = threadIdx.x & 31;
    if (w >= n) return;
    int half = l >> 4, f4 = l & 15;
    int s = g_ptr[w], e = g_ptr[w + 1];
    float4 a0 = make_float4(NEG_INF, NEG_INF, NEG_INF, NEG_INF);
    float4 a1 = make_float4(NEG_INF, NEG_INF, NEG_INF, NEG_INF);
    int p = s + half;
    for (; p + 2 < e; p += 4) {
        int r0 = g_rowS[p], r1 = g_rowS[p + 2];
        float4 h0 = *(const float4*)(x2 + r0 * F + f4 * 4);
        float4 h1 = *(const float4*)(x2 + r1 * F + f4 * 4);
        a0.x = fmaxf(a0.x, h0.x); a0.y = fmaxf(a0.y, h0.y);
        a0.z = fmaxf(a0.z, h0.z); a0.w = fmaxf(a0.w, h0.w);
        a1.x = fmaxf(a1.x, h1.x); a1.y = fmaxf(a1.y, h1.y);
        a1.z = fmaxf(a1.z, h1.z); a1.w = fmaxf(a1.w, h1.w);
    }
    if (p < e) {
        int r0 = g_rowS[p];
        float4 h0 = *(const float4*)(x2 + r0 * F + f4 * 4);
        a0.x = fmaxf(a0.x, h0.x); a0.y = fmaxf(a0.y, h0.y);
        a0.z = fmaxf(a0.z, h0.z); a0.w = fmaxf(a0.w, h0.w);
    }
    a0.x = fmaxf(a0.x, a1.x); a0.y = fmaxf(a0.y, a1.y);
    a0.z = fmaxf(a0.z, a1.z); a0.w = fmaxf(a0.w, a1.w);
    a0.x = fmaxf(a0.x, __shfl_xor_sync(0xFFFFFFFFu, a0.x, 16));
    a0.y = fmaxf(a0.y, __shfl_xor_sync(0xFFFFFFFFu, a0.y, 16));
    a0.z = fmaxf(a0.z, __shfl_xor_sync(0xFFFFFFFFu, a0.z, 16));
    a0.w = fmaxf(a0.w, __shfl_xor_sync(0xFFFFFFFFu, a0.w, 16));
    if (half == 0) *(float4*)(out + w * F + f4 * 4) = a0;
}

// softmax with fused score computation; fast path for deg<=32
__global__ void k_softmax(const float* __restrict__ attb, int n) {
    int w = (blockIdx.x * blockDim.x + threadIdx.x) >> 5;
    int l = threadIdx.x & 31;
    if (w >= n) return;
    int s = g_ptr[w], e = g_ptr[w + 1];
    float qb = g_qa[w] + attb[0];
    int deg = e - s;
    if (deg <= 32) {
        int p = s + l;
        bool act = p < e;
        float sc = NEG_INF;
        if (act) {
            sc = qb + g_pa[g_rowS[p]];
            sc = (sc >= 0.f) ? sc : 0.2f * sc;
        }
        float m = wredmax(sc);
        float ex = act ? expf(sc - m) : 0.f;
        float sum = wredsum(ex);
        if (act) g_score[p] = ex / sum;
    } else {
        float m = NEG_INF;
        for (int p = s + l; p < e; p += 32) {
            float sc = qb + g_pa[g_rowS[p]];
            sc = (sc >= 0.f) ? sc : 0.2f * sc;
            g_score[p] = sc;
            m = fmaxf(m, sc);
        }
        m = wredmax(m);
        float sum = 0.f;
        for (int p = s + l; p < e; p += 32) sum += expf(g_score[p] - m);
        sum = wredsum(sum);
        float invs = 1.f / sum;
        for (int p = s + l; p < e; p += 32) g_score[p] = expf(g_score[p] - m) * invs;
    }
}

// xc = sum score * x2[row], 4 edges in flight, fused le dots epilogue
__global__ void k_xc(const float* __restrict__ le1W, const float* __restrict__ le1b,
                     const float* __restrict__ le2W, const float* __restrict__ le3W, int n) {
    int w = (blockIdx.x * blockDim.x + threadIdx.x) >> 5;
    int l = threadIdx.x & 31;
    if (w >= n) return;
    int half = l >> 4, f4 = l & 15;
    int s = g_ptr[w], e = g_ptr[w + 1];
    float4 a0 = make_float4(0.f, 0.f, 0.f, 0.f);
    float4 a1 = make_float4(0.f, 0.f, 0.f, 0.f);
    int p = s + half;
    for (; p + 2 < e; p += 4) {
        int r0 = g_rowS[p], r1 = g_rowS[p + 2];
        float s0 = g_score[p], s1 = g_score[p + 2];
        float4 h0 = *(const float4*)(g_x2 + r0 * F + f4 * 4);
        float4 h1 = *(const float4*)(g_x2 + r1 * F + f4 * 4);
        a0.x += s0 * h0.x; a0.y += s0 * h0.y; a0.z += s0 * h0.z; a0.w += s0 * h0.w;
        a1.x += s1 * h1.x; a1.y += s1 * h1.y; a1.z += s1 * h1.z; a1.w += s1 * h1.w;
    }
    if (p < e) {
        int r0 = g_rowS[p];
        float s0 = g_score[p];
        float4 h0 = *(const float4*)(g_x2 + r0 * F + f4 * 4);
        a0.x += s0 * h0.x; a0.y += s0 * h0.y; a0.z += s0 * h0.z; a0.w += s0 * h0.w;
    }
    a0.x += a1.x; a0.y += a1.y; a0.z += a1.z; a0.w += a1.w;
    a0.x += __shfl_xor_sync(0xFFFFFFFFu, a0.x, 16);
    a0.y += __shfl_xor_sync(0xFFFFFFFFu, a0.y, 16);
    a0.z += __shfl_xor_sync(0xFFFFFFFFu, a0.z, 16);
    a0.w += __shfl_xor_sync(0xFFFFFFFFu, a0.w, 16);
    float s1 = 0.f, s2 = 0.f, s3 = 0.f;
    if (half == 0) {
        *(float4*)(g_xc + w * F + f4 * 4) = a0;
        float4 w1 = *(const float4*)(le1W + f4 * 4);
        float4 w2 = *(const float4*)(le2W + f4 * 4);
        float4 w3 = *(const float4*)(le3W + f4 * 4);
        s1 = a0.x * w1.x + a0.y * w1.y + a0.z * w1.z + a0.w * w1.w;
        s2 = a0.x * w2.x + a0.y * w2.y + a0.z * w2.z + a0.w * w2.w;
        s3 = a0.x * w3.x + a0.y * w3.y + a0.z * w3.z + a0.w * w3.w;
    }
    s1 = wredsum(s1); s2 = wredsum(s2); s3 = wredsum(s3);
    if (l == 0) { g_av[w] = s1 + le1b[0]; g_bv[w] = s2; g_cv[w] = s3; }
}

__global__ void k_fitness(const float* __restrict__ le3b, int n) {
    int w = (blockIdx.x * blockDim.x + threadIdx.x) >> 5;
    int l = threadIdx.x & 31;
    if (w >= n) return;
    int s = g_ptr[w], e = g_ptr[w + 1];
    float sum = 0.f;
    for (int p = s + l; p < e; p += 32) sum += g_av[g_rowS[p]];
    sum = wredsum(sum);
    if (l == 0) {
        float deg = (float)(e - s);
        float val = sum - deg * g_bv[w] + g_cv[w] + le3b[0];
        g_fit[w] = 1.f / (1.f + expf(-val));
    }
}

// ---------------- exact top-K (jax semantics) ----------------
__global__ void __launch_bounds__(1024) k_topk1(int n) {
    __shared__ unsigned long long s[2048];
    int t = threadIdx.x;
    int base = blockIdx.x * 2048;
    for (int j = t; j < 2048; j += 1024) {
        int i = base + j;
        s[j] = (i < n) ? make_key(g_fit[i], i) : 0ULL;
    }
    __syncthreads();
    bitonic_desc<2048>(s);
    if (t < 256) g_cand[blockIdx.x * 256 + t] = s[t];
}

__global__ void __launch_bounds__(1024) k_topk2(int n2) {
    __shared__ unsigned long long s[4096];
    int t = threadIdx.x;
    for (int j = t; j < 4096; j += 1024) s[j] = (j < n2) ? g_cand[j] : 0ULL;
    __syncthreads();
    bitonic_desc<4096>(s);
    if (t < KSEL) {
        unsigned long long key = s[t];
        int idx = (int)(0xFFFFFFFFu - (unsigned)(key & 0xFFFFFFFFu));
        g_perm[t] = idx;
        g_fitk[t] = g_fit[idx];
        g_inv[idx] = t + 1;   // 0 = not selected
    }
}

// ---------------- sparse S entries + AS scatter (node-parallel, warp/node) ----
__global__ void k_entries(int n) {
    int w = (blockIdx.x * blockDim.x + threadIdx.x) >> 5;
    int l = threadIdx.x & 31;
    if (w >= n) return;
    int kk = g_inv[w];
    if (kk == 0) return;
    int k = kk - 1;
    int s = g_ptr[w], e = g_ptr[w + 1];
    for (int p = s + l; p < e; p += 32) {
        int r = g_rowS[p];
        float val = g_score[p];
        int idx = atomicAdd(&g_nent, 1);
        g_entR[idx] = r;
        g_entK[idx] = k;
        g_entV[idx] = val;
        int s2 = g_ptr[r], e2 = g_ptr[r + 1];
        for (int q = s2; q < e2; q++)
            atomicAdd(&g_AS[(size_t)g_rowS[q] * KSEL + k], val);
    }
}

__global__ void k_Anew(float* __restrict__ outA) {
    int w = (blockIdx.x * blockDim.x + threadIdx.x) >> 5;
    int l = threadIdx.x & 31;
    int nw = (gridDim.x * blockDim.x) >> 5;
    int ne = g_nent;
    for (int i = w; i < ne; i += nw) {
        int r = g_entR[i];
        int k1 = g_entK[i];
        float v = g_entV[i];
        const float4* asr = (const float4*)(g_AS + (size_t)r * KSEL);
        float4 x0 = asr[l * 2], x1 = asr[l * 2 + 1];
        float* dst = outA + k1 * KSEL + l * 8;
        atomicAdd(dst + 0, v * x0.x);
        atomicAdd(dst + 1, v * x0.y);
        atomicAdd(dst + 2, v * x0.z);
        atomicAdd(dst + 3, v * x0.w);
        atomicAdd(dst + 4, v * x1.x);
        atomicAdd(dst + 5, v * x1.y);
        atomicAdd(dst + 6, v * x1.z);
        atomicAdd(dst + 7, v * x1.w);
    }
}

// final outputs; also restores g_inv/g_nent to zero for next replay
__global__ void k_final(float* __restrict__ out) {
    int t = blockIdx.x * blockDim.x + threadIdx.x;
    if (t < KSEL * F) {
        int k = t / F, f = t % F;
        out[t] = g_xc[g_perm[k] * F + f] * g_fitk[k];
    }
    if (t < KSEL) {
        out[KSEL * F + KSEL * KSEL + t] = (float)g_perm[t];
        out[KSEL * F + t * KSEL + t] = 1.0f;
        g_inv[g_perm[t]] = 0;
    }
    if (t == 0) g_nent = 0;
}

// ---------------- launch ----------------
extern "C" void kernel_launch(void* const* d_in, const int* in_sizes, int n_in,
                              void* d_out, int out_size) {
    const float* x     = (const float*)d_in[0];
    const int*   ei    = (const int*)d_in[1];
    const float* W0    = (const float*)d_in[2];
    const float* b0    = (const float*)d_in[3];
    const float* W1    = (const float*)d_in[4];
    const float* b1    = (const float*)d_in[5];
    const float* linW  = (const float*)d_in[6];
    const float* linb  = (const float*)d_in[7];
    const float* attW  = (const float*)d_in[8];
    const float* attb  = (const float*)d_in[9];
    const float* le1W  = (const float*)d_in[10];
    const float* le1b  = (const float*)d_in[11];
    const float* le2W  = (const float*)d_in[12];
    const float* le3W  = (const float*)d_in[13];
    const float* le3b  = (const float*)d_in[14];
    float* out = (float*)d_out;

    int N  = in_sizes[0] / F;
    int E  = in_sizes[1] / 2;
    int Et = E + N;

    void* vp;
    cudaGetSymbolAddress(&vp, g_h);   float* p_h   = (float*)vp;
    cudaGetSymbolAddress(&vp, g_x1);  float* p_x1  = (float*)vp;
    cudaGetSymbolAddress(&vp, g_x2);  float* p_x2  = (float*)vp;
    cudaGetSymbolAddress(&vp, g_xqp); float* p_xqp = (float*)vp;
    cudaGetSymbolAddress(&vp, g_xq);  float* p_xq  = (float*)vp;
    cudaGetSymbolAddress(&vp, g_AS);  void*  p_AS  = vp;

    cudaMemsetAsync(p_AS, 0, (size_t)N * KSEL * sizeof(float));
    cudaMemsetAsync(out + KSEL * F, 0, (size_t)KSEL * KSEL * sizeof(float));

    int eB  = (E + 255) / 256;
    int tEB = (Et + 255) / 256;
    int nWB = (N + 7) / 8;        // warp-per-node (256 thr = 8 warps)
    int mmB = (N + 31) / 32;

    k_count<<<eB, 256>>>(ei, E);
    k_scan<<<1, 1024>>>(N);
    k_scatter<<<tEB, 256>>>(ei, E, N);

    k_matmul<<<mmB, 256>>>(x, W0, nullptr, p_h, N);
    k_gcnagg<false><<<nWB, 256>>>(p_h, b0, nullptr, p_x1, N);
    k_matmul<<<mmB, 256>>>(p_x1, W1, nullptr, p_h, N);
    k_gcnagg<true><<<nWB, 256>>>(p_h, b1, attW, p_x2, N);

    k_segmax<<<nWB, 256>>>(p_x2, p_xqp, N);
    k_matmul_qa<<<mmB, 256>>>(p_xqp, linW, linb, attW, p_xq, N);
    k_softmax<<<nWB, 256>>>(attb, N);
    k_xc<<<nWB, 256>>>(le1W, le1b, le2W, le3W, N);
    k_fitness<<<nWB, 256>>>(le3b, N);

    int nb1 = (N + 2047) / 2048;
    k_topk1<<<nb1, 1024>>>(N);
    k_topk2<<<1, 1024>>>(nb1 * 256);

    k_entries<<<nWB, 256>>>(N);
    k_Anew<<<512, 256>>>(out + KSEL * F);
    k_final<<<(KSEL * F + 255) / 256, 256>>>(out);

    (void)n_in; (void)out_size;
}

// round 7
// speedup vs baseline: 1.1593x; 1.0822x over previous
#include <cuda_runtime.h>
#include <math.h>

#define F 64
#define KSEL 256
#define NMAX 20000
#define EMAX 320000
#define ETMAX (NMAX + EMAX)
#define NEG_INF (-3.402823466e38f)
#define XS 68   // padded smem row stride (floats); 68*4=272B, 16B aligned, bank-skewed

// ---------------- scratch (static __device__, zero-initialized) ----------------
__device__ float g_h[NMAX * F];
__device__ float g_x1[NMAX * F];
__device__ float g_x2[NMAX * F];
__device__ float g_xc[NMAX * F];
__device__ float g_dis[NMAX];
__device__ float g_qa[NMAX], g_pa[NMAX];
__device__ float g_av[NMAX], g_bv[NMAX], g_cv[NMAX], g_fit[NMAX];
__device__ float g_score[ETMAX];
__device__ int   g_rowS[ETMAX];
__device__ int   g_cnt[NMAX], g_ptr[NMAX + 1], g_wofs[NMAX], g_inv[NMAX];
__device__ unsigned long long g_cand[16 * 256];
__device__ int   g_perm[KSEL];
__device__ float g_fitk[KSEL];
__device__ int   g_entR[ETMAX], g_entK[ETMAX];
__device__ float g_entV[ETMAX];
__device__ int   g_nent;
__device__ float g_vq[F + 1];   // v = linW @ attW[0:F], last = linb . attW[0:F]
__device__ float g_AS[(size_t)NMAX * KSEL];

// ---------------- helpers ----------------
__device__ __forceinline__ float wredsum(float v) {
    #pragma unroll
    for (int d = 16; d; d >>= 1) v += __shfl_xor_sync(0xFFFFFFFFu, v, d);
    return v;
}
__device__ __forceinline__ float wredmax(float v) {
    #pragma unroll
    for (int d = 16; d; d >>= 1) v = fmaxf(v, __shfl_xor_sync(0xFFFFFFFFu, v, d));
    return v;
}
__device__ __forceinline__ unsigned long long make_key(float f, int i) {
    unsigned u = __float_as_uint(f);
    u = (u & 0x80000000u) ? ~u : (u | 0x80000000u);
    return ((unsigned long long)u << 32) | (unsigned)(0xFFFFFFFFu - (unsigned)i);
}
template <int NSORT>
__device__ void bitonic_desc(unsigned long long* s) {
    int t = threadIdx.x;
    for (int k = 2; k <= NSORT; k <<= 1) {
        for (int j = k >> 1; j > 0; j >>= 1) {
            for (int i = t; i < NSORT; i += blockDim.x) {
                int ixj = i ^ j;
                if (ixj > i) {
                    unsigned long long a = s[i], b = s[ixj];
                    bool sw = ((i & k) == 0) ? (a < b) : (a > b);
                    if (sw) { s[i] = b; s[ixj] = a; }
                }
            }
            __syncthreads();
        }
    }
}

// ---------------- CSR build ----------------
__global__ void k_count(const int* __restrict__ ei, int E) {
    int e = blockIdx.x * blockDim.x + threadIdx.x;
    if (e >= E) return;
    atomicAdd(&g_cnt[ei[E + e]], 1);
}

// scan (counts+1) -> ptr/wofs, deg -> dis; RESETS g_cnt to 0 after reading
__global__ void __launch_bounds__(1024) k_scan(int Nn) {
    __shared__ int warpsum[32];
    int t = threadIdx.x, lane = t & 31, wid = t >> 5;
    int offset = 0;
    for (int base = 0; base < Nn; base += 1024) {
        int i = base + t;
        int v = 0;
        if (i < Nn) { v = g_cnt[i] + 1; g_cnt[i] = 0; }
        int x = v;
        #pragma unroll
        for (int d = 1; d < 32; d <<= 1) {
            int y = __shfl_up_sync(0xFFFFFFFFu, x, d);
            if (lane >= d) x += y;
        }
        if (lane == 31) warpsum[wid] = x;
        __syncthreads();
        if (wid == 0) {
            int s = warpsum[lane];
            #pragma unroll
            for (int d = 1; d < 32; d <<= 1) {
                int y = __shfl_up_sync(0xFFFFFFFFu, s, d);
                if (lane >= d) s += y;
            }
            warpsum[lane] = s;
        }
        __syncthreads();
        int ex = x - v + (wid > 0 ? warpsum[wid - 1] : 0);
        int val = offset + ex;
        if (i < Nn) {
            g_ptr[i] = val; g_wofs[i] = val;
            g_dis[i] = rsqrtf((float)v);
        }
        offset += warpsum[31];
        __syncthreads();
    }
    if (t == 0) g_ptr[Nn] = offset;
}

__global__ void k_scatter(const int* __restrict__ ei, int E, int Nn) {
    int e = blockIdx.x * blockDim.x + threadIdx.x;
    int Et = E + Nn;
    if (e >= Et) return;
    int r, c;
    if (e < E) { r = ei[e]; c = ei[E + e]; } else { r = e - E; c = e - E; }
    int pos = atomicAdd(&g_wofs[c], 1);
    g_rowS[pos] = r;
}

// ---------------- precompute v = linW @ attW[0:F], c = linb . attW[0:F] ------
__global__ void k_prep(const float* __restrict__ linW, const float* __restrict__ linb,
                       const float* __restrict__ attW) {
    int k = threadIdx.x;
    if (k < F) {
        float s = 0.f;
        #pragma unroll 8
        for (int c = 0; c < F; c++) s += linW[k * F + c] * attW[c];
        g_vq[k] = s;
    }
    if (k == 0) {
        float s = 0.f;
        for (int c = 0; c < F; c++) s += linb[c] * attW[c];
        g_vq[F] = s;
    }
}

// ---------------- dense matmul: 64 rows/block, 4x4 register tile/thread -------
__global__ void __launch_bounds__(256) k_matmul(const float* __restrict__ X,
                                                const float* __restrict__ W,
                                                float* __restrict__ Y, int n) {
    __shared__ float Ws[F * F];
    __shared__ float Xs[64 * XS];
    int t = threadIdx.x;
    const float4* W4 = (const float4*)W;
    float4* Ws4 = (float4*)Ws;
    #pragma unroll
    for (int i = 0; i < 4; i++) Ws4[t + 256 * i] = W4[t + 256 * i];

    int r0 = blockIdx.x * 64;
    int rows = n - r0; if (rows > 64) rows = 64;
    const float4* X4 = (const float4*)(X + (size_t)r0 * F);
    for (int i = t; i < 64 * 16; i += 256) {
        int row = i >> 4, c4 = i & 15;
        float4 v = (row < rows) ? X4[row * 16 + c4] : make_float4(0.f, 0.f, 0.f, 0.f);
        *(float4*)(Xs + row * XS + c4 * 4) = v;
    }
    __syncthreads();

    int tx = t & 15, ty = t >> 4;   // tx: col-group (4 cols), ty: row-group (4 rows)
    float4 a0 = make_float4(0.f,0.f,0.f,0.f), a1 = a0, a2 = a0, a3 = a0;
    const float* xr0 = Xs + (ty * 4 + 0) * XS;
    const float* xr1 = Xs + (ty * 4 + 1) * XS;
    const float* xr2 = Xs + (ty * 4 + 2) * XS;
    const float* xr3 = Xs + (ty * 4 + 3) * XS;
    #pragma unroll 8
    for (int k = 0; k < F; k++) {
        float4 wv = *(const float4*)(Ws + k * F + tx * 4);
        float x0 = xr0[k], x1 = xr1[k], x2 = xr2[k], x3 = xr3[k];
        a0.x += x0 * wv.x; a0.y += x0 * wv.y; a0.z += x0 * wv.z; a0.w += x0 * wv.w;
        a1.x += x1 * wv.x; a1.y += x1 * wv.y; a1.z += x1 * wv.z; a1.w += x1 * wv.w;
        a2.x += x2 * wv.x; a2.y += x2 * wv.y; a2.z += x2 * wv.z; a2.w += x2 * wv.w;
        a3.x += x3 * wv.x; a3.y += x3 * wv.y; a3.z += x3 * wv.z; a3.w += x3 * wv.w;
    }
    int rb = r0 + ty * 4;
    if (rb + 0 < n) ((float4*)(Y + (size_t)(rb + 0) * F))[tx] = a0;
    if (rb + 1 < n) ((float4*)(Y + (size_t)(rb + 1) * F))[tx] = a1;
    if (rb + 2 < n) ((float4*)(Y + (size_t)(rb + 2) * F))[tx] = a2;
    if (rb + 3 < n) ((float4*)(Y + (size_t)(rb + 3) * F))[tx] = a3;
}

// ---------------- segment gathers: 4 edges in flight per warp ----------------
template <bool WITH_PA>
__global__ void k_gcnagg(const float* __restrict__ h, const float* __restrict__ b,
                         const float* __restrict__ attW, float* __restrict__ out, int n) {
    int w = (blockIdx.x * blockDim.x + threadIdx.x) >> 5;
    int l = threadIdx.x & 31;
    if (w >= n) return;
    int half = l >> 4, f4 = l & 15;
    int s = g_ptr[w], e = g_ptr[w + 1];
    float dc = g_dis[w];
    float4 a0 = make_float4(0.f, 0.f, 0.f, 0.f);
    float4 a1 = make_float4(0.f, 0.f, 0.f, 0.f);
    int p = s + half;
    for (; p + 2 < e; p += 4) {
        int r0 = g_rowS[p], r1 = g_rowS[p + 2];
        float n0 = dc * g_dis[r0], n1 = dc * g_dis[r1];
        float4 h0 = *(const float4*)(h + r0 * F + f4 * 4);
        float4 h1 = *(const float4*)(h + r1 * F + f4 * 4);
        a0.x += n0 * h0.x; a0.y += n0 * h0.y; a0.z += n0 * h0.z; a0.w += n0 * h0.w;
        a1.x += n1 * h1.x; a1.y += n1 * h1.y; a1.z += n1 * h1.z; a1.w += n1 * h1.w;
    }
    if (p < e) {
        int r0 = g_rowS[p];
        float n0 = dc * g_dis[r0];
        float4 h0 = *(const float4*)(h + r0 * F + f4 * 4);
        a0.x += n0 * h0.x; a0.y += n0 * h0.y; a0.z += n0 * h0.z; a0.w += n0 * h0.w;
    }
    a0.x += a1.x; a0.y += a1.y; a0.z += a1.z; a0.w += a1.w;
    a0.x += __shfl_xor_sync(0xFFFFFFFFu, a0.x, 16);
    a0.y += __shfl_xor_sync(0xFFFFFFFFu, a0.y, 16);
    a0.z += __shfl_xor_sync(0xFFFFFFFFu, a0.z, 16);
    a0.w += __shfl_xor_sync(0xFFFFFFFFu, a0.w, 16);
    float4 bb = *(const float4*)(b + f4 * 4);
    a0.x = fmaxf(a0.x + bb.x, 0.f);
    a0.y = fmaxf(a0.y + bb.y, 0.f);
    a0.z = fmaxf(a0.z + bb.z, 0.f);
    a0.w = fmaxf(a0.w + bb.w, 0.f);
    if (half == 0) *(float4*)(out + w * F + f4 * 4) = a0;
    if (WITH_PA) {
        float part = 0.f;
        if (half == 0) {
            float4 aw = *(const float4*)(attW + F + f4 * 4);
            part = a0.x * aw.x + a0.y * aw.y + a0.z * aw.z + a0.w * aw.w;
        }
        part = wredsum(part);
        if (l == 0) g_pa[w] = part;
    }
}

// segmax over x2 with fused qa = row . v + c epilogue (no global row store)
__global__ void k_segmax_qa(const float* __restrict__ x2, int n) {
    int w = (blockIdx.x * blockDim.x + threadIdx.x) >> 5;
    int l = threadIdx.x & 31;
    if (w >= n) return;
    int half = l >> 4, f4 = l & 15;
    int s = g_ptr[w], e = g_ptr[w + 1];
    float4 a0 = make_float4(NEG_INF, NEG_INF, NEG_INF, NEG_INF);
    float4 a1 = make_float4(NEG_INF, NEG_INF, NEG_INF, NEG_INF);
    int p = s + half;
    for (; p + 2 < e; p += 4) {
        int r0 = g_rowS[p], r1 = g_rowS[p + 2];
        float4 h0 = *(const float4*)(x2 + r0 * F + f4 * 4);
        float4 h1 = *(const float4*)(x2 + r1 * F + f4 * 4);
        a0.x = fmaxf(a0.x, h0.x); a0.y = fmaxf(a0.y, h0.y);
        a0.z = fmaxf(a0.z, h0.z); a0.w = fmaxf(a0.w, h0.w);
        a1.x = fmaxf(a1.x, h1.x); a1.y = fmaxf(a1.y, h1.y);
        a1.z = fmaxf(a1.z, h1.z); a1.w = fmaxf(a1.w, h1.w);
    }
    if (p < e) {
        int r0 = g_rowS[p];
        float4 h0 = *(const float4*)(x2 + r0 * F + f4 * 4);
        a0.x = fmaxf(a0.x, h0.x); a0.y = fmaxf(a0.y, h0.y);
        a0.z = fmaxf(a0.z, h0.z); a0.w = fmaxf(a0.w, h0.w);
    }
    a0.x = fmaxf(a0.x, a1.x); a0.y = fmaxf(a0.y, a1.y);
    a0.z = fmaxf(a0.z, a1.z); a0.w = fmaxf(a0.w, a1.w);
    a0.x = fmaxf(a0.x, __shfl_xor_sync(0xFFFFFFFFu, a0.x, 16));
    a0.y = fmaxf(a0.y, __shfl_xor_sync(0xFFFFFFFFu, a0.y, 16));
    a0.z = fmaxf(a0.z, __shfl_xor_sync(0xFFFFFFFFu, a0.z, 16));
    a0.w = fmaxf(a0.w, __shfl_xor_sync(0xFFFFFFFFu, a0.w, 16));
    float part = 0.f;
    if (half == 0) {
        float4 vv = *(const float4*)(g_vq + f4 * 4);
        part = a0.x * vv.x + a0.y * vv.y + a0.z * vv.z + a0.w * vv.w;
    }
    part = wredsum(part);
    if (l == 0) g_qa[w] = part + g_vq[F];
}

// softmax with fused score computation; fast path for deg<=32
__global__ void k_softmax(const float* __restrict__ attb, int n) {
    int w = (blockIdx.x * blockDim.x + threadIdx.x) >> 5;
    int l = threadIdx.x & 31;
    if (w >= n) return;
    int s = g_ptr[w], e = g_ptr[w + 1];
    float qb = g_qa[w] + attb[0];
    int deg = e - s;
    if (deg <= 32) {
        int p = s + l;
        bool act = p < e;
        float sc = NEG_INF;
        if (act) {
            sc = qb + g_pa[g_rowS[p]];
            sc = (sc >= 0.f) ? sc : 0.2f * sc;
        }
        float m = wredmax(sc);
        float ex = act ? expf(sc - m) : 0.f;
        float sum = wredsum(ex);
        if (act) g_score[p] = ex / sum;
    } else {
        float m = NEG_INF;
        for (int p = s + l; p < e; p += 32) {
            float sc = qb + g_pa[g_rowS[p]];
            sc = (sc >= 0.f) ? sc : 0.2f * sc;
            g_score[p] = sc;
            m = fmaxf(m, sc);
        }
        m = wredmax(m);
        float sum = 0.f;
        for (int p = s + l; p < e; p += 32) sum += expf(g_score[p] - m);
        sum = wredsum(sum);
        float invs = 1.f / sum;
        for (int p = s + l; p < e; p += 32) g_score[p] = expf(g_score[p] - m) * invs;
    }
}

// xc = sum score * x2[row], 4 edges in flight, fused le dots epilogue
__global__ void k_xc(const float* __restrict__ le1W, const float* __restrict__ le1b,
                     const float* __restrict__ le2W, const float* __restrict__ le3W, int n) {
    int w = (blockIdx.x * blockDim.x + threadIdx.x) >> 5;
    int l = threadIdx.x & 31;
    if (w >= n) return;
    int half = l >> 4, f4 = l & 15;
    int s = g_ptr[w], e = g_ptr[w + 1];
    float4 a0 = make_float4(0.f, 0.f, 0.f, 0.f);
    float4 a1 = make_float4(0.f, 0.f, 0.f, 0.f);
    int p = s + half;
    for (; p + 2 < e; p += 4) {
        int r0 = g_rowS[p], r1 = g_rowS[p + 2];
        float s0 = g_score[p], s1 = g_score[p + 2];
        float4 h0 = *(const float4*)(g_x2 + r0 * F + f4 * 4);
        float4 h1 = *(const float4*)(g_x2 + r1 * F + f4 * 4);
        a0.x += s0 * h0.x; a0.y += s0 * h0.y; a0.z += s0 * h0.z; a0.w += s0 * h0.w;
        a1.x += s1 * h1.x; a1.y += s1 * h1.y; a1.z += s1 * h1.z; a1.w += s1 * h1.w;
    }
    if (p < e) {
        int r0 = g_rowS[p];
        float s0 = g_score[p];
        float4 h0 = *(const float4*)(g_x2 + r0 * F + f4 * 4);
        a0.x += s0 * h0.x; a0.y += s0 * h0.y; a0.z += s0 * h0.z; a0.w += s0 * h0.w;
    }
    a0.x += a1.x; a0.y += a1.y; a0.z += a1.z; a0.w += a1.w;
    a0.x += __shfl_xor_sync(0xFFFFFFFFu, a0.x, 16);
    a0.y += __shfl_xor_sync(0xFFFFFFFFu, a0.y, 16);
    a0.z += __shfl_xor_sync(0xFFFFFFFFu, a0.z, 16);
    a0.w += __shfl_xor_sync(0xFFFFFFFFu, a0.w, 16);
    float s1 = 0.f, s2 = 0.f, s3 = 0.f;
    if (half == 0) {
        *(float4*)(g_xc + w * F + f4 * 4) = a0;
        float4 w1 = *(const float4*)(le1W + f4 * 4);
        float4 w2 = *(const float4*)(le2W + f4 * 4);
        float4 w3 = *(const float4*)(le3W + f4 * 4);
        s1 = a0.x * w1.x + a0.y * w1.y + a0.z * w1.z + a0.w * w1.w;
        s2 = a0.x * w2.x + a0.y * w2.y + a0.z * w2.z + a0.w * w2.w;
        s3 = a0.x * w3.x + a0.y * w3.y + a0.z * w3.z + a0.w * w3.w;
    }
    s1 = wredsum(s1); s2 = wredsum(s2); s3 = wredsum(s3);
    if (l == 0) { g_av[w] = s1 + le1b[0]; g_bv[w] = s2; g_cv[w] = s3; }
}

__global__ void k_fitness(const float* __restrict__ le3b, int n) {
    int w = (blockIdx.x * blockDim.x + threadIdx.x) >> 5;
    int l = threadIdx.x & 31;
    if (w >= n) return;
    int s = g_ptr[w], e = g_ptr[w + 1];
    float sum = 0.f;
    for (int p = s + l; p < e; p += 32) sum += g_av[g_rowS[p]];
    sum = wredsum(sum);
    if (l == 0) {
        float deg = (float)(e - s);
        float val = sum - deg * g_bv[w] + g_cv[w] + le3b[0];
        g_fit[w] = 1.f / (1.f + expf(-val));
    }
}

// ---------------- exact top-K (jax semantics) ----------------
__global__ void __launch_bounds__(1024) k_topk1(int n) {
    __shared__ unsigned long long s[2048];
    int t = threadIdx.x;
    int base = blockIdx.x * 2048;
    for (int j = t; j < 2048; j += 1024) {
        int i = base + j;
        s[j] = (i < n) ? make_key(g_fit[i], i) : 0ULL;
    }
    __syncthreads();
    bitonic_desc<2048>(s);
    if (t < 256) g_cand[blockIdx.x * 256 + t] = s[t];
}

__global__ void __launch_bounds__(1024) k_topk2(int n2) {
    __shared__ unsigned long long s[4096];
    int t = threadIdx.x;
    for (int j = t; j < 4096; j += 1024) s[j] = (j < n2) ? g_cand[j] : 0ULL;
    __syncthreads();
    bitonic_desc<4096>(s);
    if (t < KSEL) {
        unsigned long long key = s[t];
        int idx = (int)(0xFFFFFFFFu - (unsigned)(key & 0xFFFFFFFFu));
        g_perm[t] = idx;
        g_fitk[t] = g_fit[idx];
        g_inv[idx] = t + 1;   // 0 = not selected
    }
}

// ---------------- sparse S entries + AS scatter (node-parallel, warp/node) ----
__global__ void k_entries(int n) {
    int w = (blockIdx.x * blockDim.x + threadIdx.x) >> 5;
    int l = threadIdx.x & 31;
    if (w >= n) return;
    int kk = g_inv[w];
    if (kk == 0) return;
    int k = kk - 1;
    int s = g_ptr[w], e = g_ptr[w + 1];
    for (int p = s + l; p < e; p += 32) {
        int r = g_rowS[p];
        float val = g_score[p];
        int idx = atomicAdd(&g_nent, 1);
        g_entR[idx] = r;
        g_entK[idx] = k;
        g_entV[idx] = val;
        int s2 = g_ptr[r], e2 = g_ptr[r + 1];
        for (int q = s2; q < e2; q++)
            atomicAdd(&g_AS[(size_t)g_rowS[q] * KSEL + k], val);
    }
}

__global__ void k_Anew(float* __restrict__ outA) {
    int w = (blockIdx.x * blockDim.x + threadIdx.x) >> 5;
    int l = threadIdx.x & 31;
    int nw = (gridDim.x * blockDim.x) >> 5;
    int ne = g_nent;
    for (int i = w; i < ne; i += nw) {
        int r = g_entR[i];
        int k1 = g_entK[i];
        float v = g_entV[i];
        const float4* asr = (const float4*)(g_AS + (size_t)r * KSEL);
        float4 x0 = asr[l * 2], x1 = asr[l * 2 + 1];
        float* dst = outA + k1 * KSEL + l * 8;
        atomicAdd(dst + 0, v * x0.x);
        atomicAdd(dst + 1, v * x0.y);
        atomicAdd(dst + 2, v * x0.z);
        atomicAdd(dst + 3, v * x0.w);
        atomicAdd(dst + 4, v * x1.x);
        atomicAdd(dst + 5, v * x1.y);
        atomicAdd(dst + 6, v * x1.z);
        atomicAdd(dst + 7, v * x1.w);
    }
}

// final outputs; also restores g_inv/g_nent to zero for next replay
__global__ void k_final(float* __restrict__ out) {
    int t = blockIdx.x * blockDim.x + threadIdx.x;
    if (t < KSEL * F) {
        int k = t / F, f = t % F;
        out[t] = g_xc[g_perm[k] * F + f] * g_fitk[k];
    }
    if (t < KSEL) {
        out[KSEL * F + KSEL * KSEL + t] = (float)g_perm[t];
        out[KSEL * F + t * KSEL + t] = 1.0f;
        g_inv[g_perm[t]] = 0;
    }
    if (t == 0) g_nent = 0;
}

// ---------------- launch ----------------
extern "C" void kernel_launch(void* const* d_in, const int* in_sizes, int n_in,
                              void* d_out, int out_size) {
    const float* x     = (const float*)d_in[0];
    const int*   ei    = (const int*)d_in[1];
    const float* W0    = (const float*)d_in[2];
    const float* b0    = (const float*)d_in[3];
    const float* W1    = (const float*)d_in[4];
    const float* b1    = (const float*)d_in[5];
    const float* linW  = (const float*)d_in[6];
    const float* linb  = (const float*)d_in[7];
    const float* attW  = (const float*)d_in[8];
    const float* attb  = (const float*)d_in[9];
    const float* le1W  = (const float*)d_in[10];
    const float* le1b  = (const float*)d_in[11];
    const float* le2W  = (const float*)d_in[12];
    const float* le3W  = (const float*)d_in[13];
    const float* le3b  = (const float*)d_in[14];
    float* out = (float*)d_out;

    int N  = in_sizes[0] / F;
    int E  = in_sizes[1] / 2;
    int Et = E + N;

    void* vp;
    cudaGetSymbolAddress(&vp, g_h);   float* p_h  = (float*)vp;
    cudaGetSymbolAddress(&vp, g_x1);  float* p_x1 = (float*)vp;
    cudaGetSymbolAddress(&vp, g_x2);  float* p_x2 = (float*)vp;
    cudaGetSymbolAddress(&vp, g_AS);  void*  p_AS = vp;

    cudaMemsetAsync(p_AS, 0, (size_t)N * KSEL * sizeof(float));
    cudaMemsetAsync(out + KSEL * F, 0, (size_t)KSEL * KSEL * sizeof(float));

    int eB  = (E + 255) / 256;
    int tEB = (Et + 255) / 256;
    int nWB = (N + 7) / 8;        // warp-per-node (256 thr = 8 warps)
    int mmB = (N + 63) / 64;      // 64 rows per matmul block

    k_prep<<<1, 64>>>(linW, linb, attW);
    k_count<<<eB, 256>>>(ei, E);
    k_scan<<<1, 1024>>>(N);
    k_scatter<<<tEB, 256>>>(ei, E, N);

    k_matmul<<<mmB, 256>>>(x, W0, p_h, N);
    k_gcnagg<false><<<nWB, 256>>>(p_h, b0, nullptr, p_x1, N);
    k_matmul<<<mmB, 256>>>(p_x1, W1, p_h, N);
    k_gcnagg<true><<<nWB, 256>>>(p_h, b1, attW, p_x2, N);

    k_segmax_qa<<<nWB, 256>>>(p_x2, N);
    k_softmax<<<nWB, 256>>>(attb, N);
    k_xc<<<nWB, 256>>>(le1W, le1b, le2W, le3W, N);
    k_fitness<<<nWB, 256>>>(le3b, N);

    int nb1 = (N + 2047) / 2048;
    k_topk1<<<nb1, 1024>>>(N);
    k_topk2<<<1, 1024>>>(nb1 * 256);

    k_entries<<<nWB, 256>>>(N);
    k_Anew<<<512, 256>>>(out + KSEL * F);
    k_final<<<(KSEL * F + 255) / 256, 256>>>(out);

    (void)n_in; (void)out_size;
}